// round 4
// baseline (speedup 1.0000x reference)
#include <cuda_runtime.h>
#include <cstdint>

// ============================================================================
// QAttention_without_softmax (B=4, N=2048, C=768, H=12, D=64, LEVEL=8)
//
// Structure exploited (runtime-verified on device, general fallback included):
//   iq,ik in [-4,3]  =>  |sum_d iq*ik| <= 64*16 = 1024
//   t = 0.125*s_q*s_k*sum/(N*s_attn); if |t|_max < 0.5 then
//   round(clip(t,0,7)) == 0 for ALL elements => out == 0 => fq(out)==0
//   => final = bproj broadcast, independent of x and Wqkv.
// With the benchmark scales |t|_max = 0.4375, so the fast path is exact.
// Otherwise, a full honest pipeline runs:
//   fp32 tiled qkv GEMM -> int8 quantized q/k/v -> EXACT int8 dp4a
//   attention (quantized values are small integers, int32 accum is exact)
//   -> fp32 tiled proj GEMM + bias.
// ============================================================================

#define B_  4
#define N_  2048
#define C_  768
#define H_  12
#define D_  64

// scratch (__device__ globals; no allocation anywhere)
__device__ int   g_skip;
__device__ int   g_q[48 * 2048 * 16];   // int8 [bh][n][d], packed 4/word
__device__ int   g_k[48 * 2048 * 16];   // int8 [bh][n][d]
__device__ int   g_v[48 * 64 * 512];    // int8 [bh][d][m], packed 4/word (transposed)
__device__ float g_xo[8192 * 768];      // quantized attention output, [B,N,C]

// ---------------------------------------------------------------------------
// K0: decide whether the attention fake-quant provably yields all-zeros.
// ---------------------------------------------------------------------------
__global__ void k_decide(const float* sq, const float* sk, const float* sattn) {
    // |t|_max = 0.125 * |s_q*s_k| * 1024 / (N * |s_attn|)
    float T = fabsf(sq[0] * sk[0]) * 128.0f / (2048.0f * fabsf(sattn[0]));
    g_skip = (T < 0.4999f) ? 1 : 0;
}

// ---------------------------------------------------------------------------
// K1: qkv = x @ Wqkv^T, then per-tensor fake-quant -> int8 q/k/v scratch.
//     64x64 tile, 256 threads, 4x4 per-thread microtile.
// ---------------------------------------------------------------------------
__global__ void k_qkv(const float* __restrict__ x, const float* __restrict__ W,
                      const float* sqp, const float* skp, const float* svp) {
    if (g_skip) return;
    __shared__ float As[16][65], Bs[16][65];
    const int tx = threadIdx.x, ty = threadIdx.y;
    const int tid = ty * 16 + tx;
    const int j0 = blockIdx.x * 64;   // column in [0, 2304)
    const int m0 = blockIdx.y * 64;   // row    in [0, 8192)

    float acc[4][4] = {};
    for (int k0 = 0; k0 < C_; k0 += 16) {
        for (int l = tid; l < 64 * 16; l += 256) {
            int m = l >> 4, k = l & 15;
            As[k][m] = x[(long)(m0 + m) * C_ + k0 + k];
            Bs[k][m] = W[(long)(j0 + m) * C_ + k0 + k];
        }
        __syncthreads();
#pragma unroll
        for (int kk = 0; kk < 16; kk++) {
            float a[4], b[4];
#pragma unroll
            for (int i = 0; i < 4; i++) a[i] = As[kk][ty * 4 + i];
#pragma unroll
            for (int j = 0; j < 4; j++) b[j] = Bs[kk][tx * 4 + j];
#pragma unroll
            for (int i = 0; i < 4; i++)
#pragma unroll
                for (int j = 0; j < 4; j++) acc[i][j] += a[i] * b[j];
        }
        __syncthreads();
    }

    const float s_q = sqp[0], s_k = skp[0], s_v = svp[0];
#pragma unroll
    for (int i = 0; i < 4; i++) {
        int m = m0 + ty * 4 + i;
        int b = m / N_, n = m - b * N_;
#pragma unroll
        for (int j = 0; j < 4; j++) {
            int jj = j0 + tx * 4 + j;
            int three = jj / C_;
            int rem = jj - three * C_;
            int h = rem >> 6, d = rem & 63;
            long bh = (long)b * H_ + h;
            float val = acc[i][j];
            if (three == 0) {
                float t = fminf(fmaxf(val / s_q, -4.0f), 3.0f);
                ((int8_t*)g_q)[(bh * N_ + n) * D_ + d] = (int8_t)(int)rintf(t);
            } else if (three == 1) {
                float t = fminf(fmaxf(val / s_k, -4.0f), 3.0f);
                ((int8_t*)g_k)[(bh * N_ + n) * D_ + d] = (int8_t)(int)rintf(t);
            } else {
                float t = fminf(fmaxf(val / s_v, -4.0f), 3.0f);
                ((int8_t*)g_v)[(bh * D_ + d) * N_ + n] = (int8_t)(int)rintf(t);
            }
        }
    }
}

// ---------------------------------------------------------------------------
// K2: fused attention (no softmax) with EXACT int8 dp4a arithmetic.
//     Per block: one (b,h), one 64-row n-tile; loop over 64-wide m-tiles.
//     S = iq.ik (int32 exact) -> fake-quant to a in [0,7]
//     O += a @ v (int32 exact) -> dequant -> fake-quant(s_after) -> g_xo.
// ---------------------------------------------------------------------------
__global__ void k_attn(const float* sqp, const float* skp, const float* svp,
                       const float* sap, const float* sfp) {
    if (g_skip) return;
    __shared__ int qs[64][16], ks[64][16], as_[64][16], vs[64][16];
    const int tx = threadIdx.x, ty = threadIdx.y;
    const int tid = ty * 16 + tx;
    const int bh = blockIdx.x;           // 0..47
    const int n0 = blockIdx.y * 64;      // n tile

    const int* qw = g_q + (long)bh * N_ * 16;
    const int* kw = g_k + (long)bh * N_ * 16;
    const int* vw = g_v + (long)bh * D_ * (N_ / 4);

    for (int l = tid; l < 64 * 16; l += 256) {
        int r = l >> 4, c = l & 15;
        qs[r][c] = qw[(n0 + r) * 16 + c];
    }

    const float s_q = sqp[0], s_k = skp[0], s_v = svp[0];
    const float s_attn = sap[0], s_after = sfp[0];
    const float cs = 0.125f * s_q * s_k / ((float)N_ * s_attn);

    int o[4][4] = {};
    for (int m0 = 0; m0 < N_; m0 += 64) {
        for (int l = tid; l < 64 * 16; l += 256) {
            int r = l >> 4, c = l & 15;
            ks[r][c] = kw[(m0 + r) * 16 + c];
            vs[r][c] = vw[r * (N_ / 4) + (m0 >> 2) + c];
        }
        __syncthreads();

        int s[4][4] = {};
#pragma unroll
        for (int c = 0; c < 16; c++) {
            int a[4], b[4];
#pragma unroll
            for (int i = 0; i < 4; i++) a[i] = qs[ty * 4 + i][c];
#pragma unroll
            for (int j = 0; j < 4; j++) b[j] = ks[tx * 4 + j][c];
#pragma unroll
            for (int i = 0; i < 4; i++)
#pragma unroll
                for (int j = 0; j < 4; j++) s[i][j] = __dp4a(a[i], b[j], s[i][j]);
        }

        // fake-quant attn -> a in [0,7], pack 4 bytes/word along m
#pragma unroll
        for (int i = 0; i < 4; i++) {
            unsigned w = 0;
#pragma unroll
            for (int j = 0; j < 4; j++) {
                float t = fminf(fmaxf((float)s[i][j] * cs, 0.0f), 7.0f);
                w |= ((unsigned)(int)rintf(t)) << (8 * j);
            }
            as_[ty * 4 + i][tx] = (int)w;
        }
        __syncthreads();

#pragma unroll
        for (int c = 0; c < 16; c++) {
            int a[4], b[4];
#pragma unroll
            for (int i = 0; i < 4; i++) a[i] = as_[ty * 4 + i][c];
#pragma unroll
            for (int j = 0; j < 4; j++) b[j] = vs[tx * 4 + j][c];
#pragma unroll
            for (int i = 0; i < 4; i++)
#pragma unroll
                for (int j = 0; j < 4; j++) o[i][j] = __dp4a(a[i], b[j], o[i][j]);
        }
        __syncthreads();
    }

    const int b = bh / H_, h = bh - b * H_;
    const float ovs = s_attn * s_v;
#pragma unroll
    for (int i = 0; i < 4; i++) {
        int n = n0 + ty * 4 + i;
#pragma unroll
        for (int j = 0; j < 4; j++) {
            int d = tx * 4 + j;
            float outv = (float)o[i][j] * ovs;
            float t = fminf(fmaxf(outv / s_after, -4.0f), 3.0f);
            g_xo[((long)b * N_ + n) * C_ + h * D_ + d] = s_after * rintf(t);
        }
    }
}

// ---------------------------------------------------------------------------
// K3: out = g_xo @ Wproj^T + bproj. Fast path: bias broadcast.
// ---------------------------------------------------------------------------
__global__ void k_proj(const float* __restrict__ W, const float* __restrict__ bias,
                       float* __restrict__ out) {
    const int tx = threadIdx.x, ty = threadIdx.y;
    const int tid = ty * 16 + tx;
    const int j0 = blockIdx.x * 64;   // [0, 768)
    const int m0 = blockIdx.y * 64;   // [0, 8192)

    if (g_skip) {
        // attention fake-quant provably yields 0 => out = bproj broadcast.
        for (int l = tid; l < 64 * 64; l += 256) {
            int r = l >> 6, c = l & 63;
            out[(long)(m0 + r) * C_ + j0 + c] = bias[j0 + c];
        }
        return;
    }

    __shared__ float As[16][65], Bs[16][65];
    float acc[4][4] = {};
    for (int k0 = 0; k0 < C_; k0 += 16) {
        for (int l = tid; l < 64 * 16; l += 256) {
            int m = l >> 4, k = l & 15;
            As[k][m] = g_xo[(long)(m0 + m) * C_ + k0 + k];
            Bs[k][m] = W[(long)(j0 + m) * C_ + k0 + k];
        }
        __syncthreads();
#pragma unroll
        for (int kk = 0; kk < 16; kk++) {
            float a[4], b[4];
#pragma unroll
            for (int i = 0; i < 4; i++) a[i] = As[kk][ty * 4 + i];
#pragma unroll
            for (int j = 0; j < 4; j++) b[j] = Bs[kk][tx * 4 + j];
#pragma unroll
            for (int i = 0; i < 4; i++)
#pragma unroll
                for (int j = 0; j < 4; j++) acc[i][j] += a[i] * b[j];
        }
        __syncthreads();
    }
#pragma unroll
    for (int i = 0; i < 4; i++) {
        int m = m0 + ty * 4 + i;
#pragma unroll
        for (int j = 0; j < 4; j++) {
            int jj = j0 + tx * 4 + j;
            out[(long)m * C_ + jj] = acc[i][j] + bias[jj];
        }
    }
}

// ---------------------------------------------------------------------------
extern "C" void kernel_launch(void* const* d_in, const int* in_sizes, int n_in,
                              void* d_out, int out_size) {
    const float* x      = (const float*)d_in[0];
    const float* Wqkv   = (const float*)d_in[1];
    const float* Wproj  = (const float*)d_in[2];
    const float* bproj  = (const float*)d_in[3];
    const float* s_q    = (const float*)d_in[4];
    const float* s_k    = (const float*)d_in[5];
    const float* s_v    = (const float*)d_in[6];
    const float* s_attn = (const float*)d_in[7];
    const float* s_aft  = (const float*)d_in[8];
    float* out = (float*)d_out;

    dim3 thr(16, 16);
    k_decide<<<1, 1>>>(s_q, s_k, s_attn);
    k_qkv<<<dim3(2304 / 64, 8192 / 64), thr>>>(x, Wqkv, s_q, s_k, s_v);
    k_attn<<<dim3(48, N_ / 64), thr>>>(s_q, s_k, s_v, s_attn, s_aft);
    k_proj<<<dim3(C_ / 64, 8192 / 64), thr>>>(Wproj, bproj, out);
}

// round 5
// speedup vs baseline: 1.3573x; 1.3573x over previous
#include <cuda_runtime.h>
#include <cstdint>

// ============================================================================
// QAttention_without_softmax (B=4, N=2048, C=768, H=12, D=64, LEVEL=8)
//
// Structure exploited (runtime-verified per-kernel, general fallback kept):
//   iq,ik in [-4,3]  =>  |sum_d iq*ik| <= 64*16 = 1024
//   t = 0.125*s_q*s_k*sum/(N*s_attn); if |t|_max < 0.5 then
//   round(clip(t,0,7)) == 0 for ALL elements => attn-out == 0 => fq(0)==0
//   => final = bproj broadcast, independent of x and Wqkv.
// With the benchmark scales |t|_max = 0.4375 -> fast path, exact (rel_err 0).
// Fallback (any other scales): fp32 tiled qkv GEMM -> int8 q/k/v -> EXACT
// dp4a attention -> fp32 proj GEMM + bias.
//
// R4 changes vs R2 (fast-path latency):
//   - skip predicate computed inline in every kernel (k_decide removed,
//     g_skip global removed -> one fewer graph node + no dependency)
//   - k_qkv 4608->1152 CTAs, k_attn 1536->384 CTAs (block-level tile loops)
//     to cut early-exit CTA scheduling cost
//   - k_proj skip path: float4 (STG.128) broadcast, bias held in a register
// ============================================================================

#define B_  4
#define N_  2048
#define C_  768
#define H_  12
#define D_  64

// scratch (__device__ globals; no allocation anywhere)
__device__ int   g_q[48 * 2048 * 16];   // int8 [bh][n][d], packed 4/word
__device__ int   g_k[48 * 2048 * 16];   // int8 [bh][n][d]
__device__ int   g_v[48 * 64 * 512];    // int8 [bh][d][m], packed 4/word (transposed)
__device__ float g_xo[8192 * 768];      // quantized attention output, [B,N,C]

// Skip predicate: true when the attention fake-quant provably yields all 0.
__device__ __forceinline__ bool attn_is_zero(const float* sq, const float* sk,
                                             const float* sattn) {
    // |t|_max = 0.125 * |s_q*s_k| * 1024 / (N * |s_attn|)
    float T = fabsf(__ldg(sq) * __ldg(sk)) * 128.0f / (2048.0f * fabsf(__ldg(sattn)));
    return T < 0.4999f;
}

// ---------------------------------------------------------------------------
// K1: qkv = x @ Wqkv^T, fake-quant -> int8 q/k/v. Each block: one 64-wide
//     j-tile x FOUR 64-row m-tiles (loop).  Grid (36, 32) = 1152 CTAs.
// ---------------------------------------------------------------------------
__global__ void k_qkv(const float* __restrict__ x, const float* __restrict__ W,
                      const float* sqp, const float* skp, const float* sap,
                      const float* svp) {
    if (attn_is_zero(sqp, skp, sap)) return;
    __shared__ float As[16][65], Bs[16][65];
    const int tx = threadIdx.x, ty = threadIdx.y;
    const int tid = ty * 16 + tx;
    const int j0 = blockIdx.x * 64;   // column in [0, 2304)
    const float s_q = sqp[0], s_k = skp[0], s_v = svp[0];

    for (int t = 0; t < 4; t++) {
        const int m0 = (blockIdx.y * 4 + t) * 64;   // row in [0, 8192)
        float acc[4][4] = {};
        for (int k0 = 0; k0 < C_; k0 += 16) {
            for (int l = tid; l < 64 * 16; l += 256) {
                int m = l >> 4, k = l & 15;
                As[k][m] = x[(long)(m0 + m) * C_ + k0 + k];
                Bs[k][m] = W[(long)(j0 + m) * C_ + k0 + k];
            }
            __syncthreads();
#pragma unroll
            for (int kk = 0; kk < 16; kk++) {
                float a[4], b[4];
#pragma unroll
                for (int i = 0; i < 4; i++) a[i] = As[kk][ty * 4 + i];
#pragma unroll
                for (int j = 0; j < 4; j++) b[j] = Bs[kk][tx * 4 + j];
#pragma unroll
                for (int i = 0; i < 4; i++)
#pragma unroll
                    for (int j = 0; j < 4; j++) acc[i][j] += a[i] * b[j];
            }
            __syncthreads();
        }

#pragma unroll
        for (int i = 0; i < 4; i++) {
            int m = m0 + ty * 4 + i;
            int b = m / N_, n = m - b * N_;
#pragma unroll
            for (int j = 0; j < 4; j++) {
                int jj = j0 + tx * 4 + j;
                int three = jj / C_;
                int rem = jj - three * C_;
                int h = rem >> 6, d = rem & 63;
                long bh = (long)b * H_ + h;
                float val = acc[i][j];
                if (three == 0) {
                    float u = fminf(fmaxf(val / s_q, -4.0f), 3.0f);
                    ((int8_t*)g_q)[(bh * N_ + n) * D_ + d] = (int8_t)(int)rintf(u);
                } else if (three == 1) {
                    float u = fminf(fmaxf(val / s_k, -4.0f), 3.0f);
                    ((int8_t*)g_k)[(bh * N_ + n) * D_ + d] = (int8_t)(int)rintf(u);
                } else {
                    float u = fminf(fmaxf(val / s_v, -4.0f), 3.0f);
                    ((int8_t*)g_v)[(bh * D_ + d) * N_ + n] = (int8_t)(int)rintf(u);
                }
            }
        }
    }
}

// ---------------------------------------------------------------------------
// K2: fused attention with EXACT int8 dp4a arithmetic. Each block: one (b,h),
//     FOUR 64-row n-tiles (loop). Grid (48, 8) = 384 CTAs.
// ---------------------------------------------------------------------------
__global__ void k_attn(const float* sqp, const float* skp, const float* svp,
                       const float* sap, const float* sfp) {
    if (attn_is_zero(sqp, skp, sap)) return;
    __shared__ int qs[64][16], ks[64][16], as_[64][16], vs[64][16];
    const int tx = threadIdx.x, ty = threadIdx.y;
    const int tid = ty * 16 + tx;
    const int bh = blockIdx.x;           // 0..47

    const int* qw = g_q + (long)bh * N_ * 16;
    const int* kw = g_k + (long)bh * N_ * 16;
    const int* vw = g_v + (long)bh * D_ * (N_ / 4);

    const float s_q = sqp[0], s_k = skp[0], s_v = svp[0];
    const float s_attn = sap[0], s_after = sfp[0];
    const float cs = 0.125f * s_q * s_k / ((float)N_ * s_attn);
    const float ovs = s_attn * s_v;
    const int b = bh / H_, h = bh - b * H_;

    for (int t = 0; t < 4; t++) {
        const int n0 = (blockIdx.y * 4 + t) * 64;

        for (int l = tid; l < 64 * 16; l += 256) {
            int r = l >> 4, c = l & 15;
            qs[r][c] = qw[(n0 + r) * 16 + c];
        }

        int o[4][4] = {};
        for (int m0 = 0; m0 < N_; m0 += 64) {
            for (int l = tid; l < 64 * 16; l += 256) {
                int r = l >> 4, c = l & 15;
                ks[r][c] = kw[(m0 + r) * 16 + c];
                vs[r][c] = vw[r * (N_ / 4) + (m0 >> 2) + c];
            }
            __syncthreads();

            int s[4][4] = {};
#pragma unroll
            for (int c = 0; c < 16; c++) {
                int a[4], bb[4];
#pragma unroll
                for (int i = 0; i < 4; i++) a[i] = qs[ty * 4 + i][c];
#pragma unroll
                for (int j = 0; j < 4; j++) bb[j] = ks[tx * 4 + j][c];
#pragma unroll
                for (int i = 0; i < 4; i++)
#pragma unroll
                    for (int j = 0; j < 4; j++) s[i][j] = __dp4a(a[i], bb[j], s[i][j]);
            }

            // fake-quant attn -> [0,7], pack 4 bytes/word along m
#pragma unroll
            for (int i = 0; i < 4; i++) {
                unsigned w = 0;
#pragma unroll
                for (int j = 0; j < 4; j++) {
                    float u = fminf(fmaxf((float)s[i][j] * cs, 0.0f), 7.0f);
                    w |= ((unsigned)(int)rintf(u)) << (8 * j);
                }
                as_[ty * 4 + i][tx] = (int)w;
            }
            __syncthreads();

#pragma unroll
            for (int c = 0; c < 16; c++) {
                int a[4], bb[4];
#pragma unroll
                for (int i = 0; i < 4; i++) a[i] = as_[ty * 4 + i][c];
#pragma unroll
                for (int j = 0; j < 4; j++) bb[j] = vs[tx * 4 + j][c];
#pragma unroll
                for (int i = 0; i < 4; i++)
#pragma unroll
                    for (int j = 0; j < 4; j++) o[i][j] = __dp4a(a[i], bb[j], o[i][j]);
            }
            __syncthreads();
        }

#pragma unroll
        for (int i = 0; i < 4; i++) {
            int n = n0 + ty * 4 + i;
#pragma unroll
            for (int j = 0; j < 4; j++) {
                int d = tx * 4 + j;
                float outv = (float)o[i][j] * ovs;
                float u = fminf(fmaxf(outv / s_after, -4.0f), 3.0f);
                g_xo[((long)b * N_ + n) * C_ + h * D_ + d] = s_after * rintf(u);
            }
        }
    }
}

// ---------------------------------------------------------------------------
// K3: out = g_xo @ Wproj^T + bproj. Fast path: vectorized bias broadcast.
//     Grid (12, 128) = 1536 CTAs, 64x64 tile per block.
// ---------------------------------------------------------------------------
__global__ void k_proj(const float* __restrict__ W, const float* __restrict__ bias,
                       const float* sqp, const float* skp, const float* sap,
                       float* __restrict__ out) {
    const int tx = threadIdx.x, ty = threadIdx.y;
    const int tid = ty * 16 + tx;
    const int j0 = blockIdx.x * 64;   // [0, 768)
    const int m0 = blockIdx.y * 64;   // [0, 8192)

    if (attn_is_zero(sqp, skp, sap)) {
        // out = bproj broadcast; float4 stores, bias segment in a register.
        // Thread layout: col4 = tid & 15 (16 float4 = 64 floats), row = tid>>4.
        const int col4 = tid & 15;
        const int row  = tid >> 4;           // 0..15, loop 4x (rows 0..63)
        const float4 bv = ((const float4*)(bias + j0))[col4];
        float4* o4 = (float4*)(out + (long)m0 * C_ + j0) + col4;
#pragma unroll
        for (int r = 0; r < 4; r++) {
            o4[(long)(row + 16 * r) * (C_ / 4)] = bv;
        }
        return;
    }

    __shared__ float As[16][65], Bs[16][65];
    float acc[4][4] = {};
    for (int k0 = 0; k0 < C_; k0 += 16) {
        for (int l = tid; l < 64 * 16; l += 256) {
            int m = l >> 4, k = l & 15;
            As[k][m] = g_xo[(long)(m0 + m) * C_ + k0 + k];
            Bs[k][m] = W[(long)(j0 + m) * C_ + k0 + k];
        }
        __syncthreads();
#pragma unroll
        for (int kk = 0; kk < 16; kk++) {
            float a[4], b[4];
#pragma unroll
            for (int i = 0; i < 4; i++) a[i] = As[kk][ty * 4 + i];
#pragma unroll
            for (int j = 0; j < 4; j++) b[j] = Bs[kk][tx * 4 + j];
#pragma unroll
            for (int i = 0; i < 4; i++)
#pragma unroll
                for (int j = 0; j < 4; j++) acc[i][j] += a[i] * b[j];
        }
        __syncthreads();
    }
#pragma unroll
    for (int i = 0; i < 4; i++) {
        int m = m0 + ty * 4 + i;
#pragma unroll
        for (int j = 0; j < 4; j++) {
            int jj = j0 + tx * 4 + j;
            out[(long)m * C_ + jj] = acc[i][j] + bias[jj];
        }
    }
}

// ---------------------------------------------------------------------------
extern "C" void kernel_launch(void* const* d_in, const int* in_sizes, int n_in,
                              void* d_out, int out_size) {
    const float* x      = (const float*)d_in[0];
    const float* Wqkv   = (const float*)d_in[1];
    const float* Wproj  = (const float*)d_in[2];
    const float* bproj  = (const float*)d_in[3];
    const float* s_q    = (const float*)d_in[4];
    const float* s_k    = (const float*)d_in[5];
    const float* s_v    = (const float*)d_in[6];
    const float* s_attn = (const float*)d_in[7];
    const float* s_aft  = (const float*)d_in[8];
    float* out = (float*)d_out;

    dim3 thr(16, 16);
    k_qkv<<<dim3(2304 / 64, 32), thr>>>(x, Wqkv, s_q, s_k, s_attn, s_v);
    k_attn<<<dim3(48, 8), thr>>>(s_q, s_k, s_v, s_attn, s_aft);
    k_proj<<<dim3(C_ / 64, 8192 / 64), thr>>>(Wproj, bproj, s_q, s_k, s_attn, out);
}

// round 6
// speedup vs baseline: 1.8857x; 1.3893x over previous
#include <cuda_runtime.h>
#include <cstdint>

// ============================================================================
// QAttention_without_softmax (B=4, N=2048, C=768, H=12, D=64, LEVEL=8)
//
// Structure exploited (runtime-verified, general fallback kept):
//   iq,ik in [-4,3]  =>  |sum_d iq*ik| <= 64*16 = 1024
//   t = 0.125*s_q*s_k*sum/(N*s_attn); if |t|_max < 0.5 then
//   round(clip(t,0,7)) == 0 for ALL elements => attn-out == 0 => fq(0)==0
//   => final = bproj broadcast, independent of x and Wqkv.
// Benchmark scales give |t|_max = 0.4375 -> fast path, bit-exact.
//
// R5 change: SINGLE kernel launch. Fast path = float4 bias broadcast
// (L2-write-bound, ~2.5us floor). Fallback = the full exact pipeline
// (fp32 qkv GEMM -> int8 dp4a attention -> fp32 proj GEMM) executed in
// one kernel with a software grid barrier. Residency proof: grid = 592 =
// 148 SM x 4 CTA, __launch_bounds__(256,4) bounds regs/smem so 4 CTAs/SM
// always fit -> all CTAs co-resident -> barrier cannot deadlock.
// ============================================================================

#define B_    4
#define N_    2048
#define C_    768
#define H_    12
#define D_    64
#define GRID_ 592
#define ROWS_ 8192           // B*N
#define C4_   192            // C/4

// scratch (__device__ globals; no allocation anywhere)
__device__ int   g_q[48 * 2048 * 16];   // int8 [bh][n][d], packed 4/word
__device__ int   g_k[48 * 2048 * 16];   // int8 [bh][n][d]
__device__ int   g_v[48 * 64 * 512];    // int8 [bh][d][m], packed (transposed)
__device__ float g_xo[ROWS_ * C_];      // quantized attention output [B,N,C]

// grid-barrier state (fallback only; fast path never touches)
__device__ unsigned g_count = 0;
__device__ unsigned g_sense = 0;

__device__ __forceinline__ void grid_sync(unsigned& my_sense) {
    __threadfence();
    __syncthreads();
    ++my_sense;                      // every thread tracks the same sense
    if (threadIdx.x == 0) {
        unsigned arrived = atomicAdd(&g_count, 1u);
        if (arrived == GRID_ - 1u) {
            g_count = 0u;
            __threadfence();
            atomicExch(&g_sense, my_sense);
        } else {
            while (atomicAdd(&g_sense, 0u) != my_sense) __nanosleep(64);
        }
    }
    __syncthreads();
}

__global__ __launch_bounds__(256, 4)
void k_mono(const float* __restrict__ x,     const float* __restrict__ Wqkv,
            const float* __restrict__ Wproj, const float* __restrict__ bias,
            const float* sqp, const float* skp, const float* svp,
            const float* sap, const float* sfp,
            float* __restrict__ out) {
    const int tid = threadIdx.x;

    // ---- skip predicate: attention fake-quant provably all-zero? ----------
    // |t|_max = 0.125 * |s_q*s_k| * 1024 / (N * |s_attn|)
    const float s_q = __ldg(sqp), s_k = __ldg(skp), s_attn = __ldg(sap);
    const float T = fabsf(s_q * s_k) * 128.0f / (2048.0f * fabsf(s_attn));

    if (T < 0.4999f) {
        // ===== FAST PATH: out = bproj broadcast (float4, grid-stride rows) ==
        if (tid < C4_) {
            const float4 bv = ((const float4*)bias)[tid];
            float4* o4 = (float4*)out + tid;
            for (int row = blockIdx.x; row < ROWS_; row += GRID_)
                o4[(long)row * C4_] = bv;
        }
        return;
    }

    // ======================= FALLBACK (exact pipeline) ======================
    const float s_v = svp[0], s_after = sfp[0];
    const int tx = tid & 15, ty = tid >> 4;
    unsigned my_sense = atomicAdd(&g_sense, 0u);   // read before any toggle

    __shared__ union {
        struct { float As[16][65], Bs[16][65]; } g;
        struct { int qs[64][16], ks[64][16], as_[64][16], vs[64][16]; } a;
    } sm;

    // ---- Phase 1: qkv = x @ Wqkv^T, fake-quant -> int8 q/k/v --------------
    for (int tile = blockIdx.x; tile < 36 * 128; tile += GRID_) {
        const int j0 = (tile % 36) * 64;       // [0,2304)
        const int m0 = (tile / 36) * 64;       // [0,8192)
        float acc[4][4] = {};
        for (int k0 = 0; k0 < C_; k0 += 16) {
            for (int l = tid; l < 64 * 16; l += 256) {
                int m = l >> 4, k = l & 15;
                sm.g.As[k][m] = x[(long)(m0 + m) * C_ + k0 + k];
                sm.g.Bs[k][m] = Wqkv[(long)(j0 + m) * C_ + k0 + k];
            }
            __syncthreads();
#pragma unroll
            for (int kk = 0; kk < 16; kk++) {
                float a[4], b[4];
#pragma unroll
                for (int i = 0; i < 4; i++) a[i] = sm.g.As[kk][ty * 4 + i];
#pragma unroll
                for (int j = 0; j < 4; j++) b[j] = sm.g.Bs[kk][tx * 4 + j];
#pragma unroll
                for (int i = 0; i < 4; i++)
#pragma unroll
                    for (int j = 0; j < 4; j++) acc[i][j] += a[i] * b[j];
            }
            __syncthreads();
        }
#pragma unroll
        for (int i = 0; i < 4; i++) {
            int m = m0 + ty * 4 + i;
            int b = m / N_, n = m - b * N_;
#pragma unroll
            for (int j = 0; j < 4; j++) {
                int jj = j0 + tx * 4 + j;
                int three = jj / C_;
                int rem = jj - three * C_;
                int h = rem >> 6, d = rem & 63;
                long bh = (long)b * H_ + h;
                float val = acc[i][j];
                if (three == 0) {
                    float u = fminf(fmaxf(val / s_q, -4.0f), 3.0f);
                    ((int8_t*)g_q)[(bh * N_ + n) * D_ + d] = (int8_t)(int)rintf(u);
                } else if (three == 1) {
                    float u = fminf(fmaxf(val / s_k, -4.0f), 3.0f);
                    ((int8_t*)g_k)[(bh * N_ + n) * D_ + d] = (int8_t)(int)rintf(u);
                } else {
                    float u = fminf(fmaxf(val / s_v, -4.0f), 3.0f);
                    ((int8_t*)g_v)[(bh * D_ + d) * N_ + n] = (int8_t)(int)rintf(u);
                }
            }
        }
    }

    grid_sync(my_sense);

    // ---- Phase 2: exact int8 dp4a attention -------------------------------
    const float cs  = 0.125f * s_q * s_k / ((float)N_ * s_attn);
    const float ovs = s_attn * s_v;
    for (int u = blockIdx.x; u < 48 * 32; u += GRID_) {
        const int bh = u >> 5;                 // 0..47
        const int n0 = (u & 31) * 64;
        const int* qw = g_q + (long)bh * N_ * 16;
        const int* kw = g_k + (long)bh * N_ * 16;
        const int* vw = g_v + (long)bh * D_ * (N_ / 4);
        const int b = bh / H_, h = bh - b * H_;

        __syncthreads();
        for (int l = tid; l < 64 * 16; l += 256) {
            int r = l >> 4, c = l & 15;
            sm.a.qs[r][c] = qw[(n0 + r) * 16 + c];
        }

        int o[4][4] = {};
        for (int m0 = 0; m0 < N_; m0 += 64) {
            for (int l = tid; l < 64 * 16; l += 256) {
                int r = l >> 4, c = l & 15;
                sm.a.ks[r][c] = kw[(m0 + r) * 16 + c];
                sm.a.vs[r][c] = vw[r * (N_ / 4) + (m0 >> 2) + c];
            }
            __syncthreads();

            int s[4][4] = {};
#pragma unroll
            for (int c = 0; c < 16; c++) {
                int a[4], bb[4];
#pragma unroll
                for (int i = 0; i < 4; i++) a[i] = sm.a.qs[ty * 4 + i][c];
#pragma unroll
                for (int j = 0; j < 4; j++) bb[j] = sm.a.ks[tx * 4 + j][c];
#pragma unroll
                for (int i = 0; i < 4; i++)
#pragma unroll
                    for (int j = 0; j < 4; j++) s[i][j] = __dp4a(a[i], bb[j], s[i][j]);
            }
#pragma unroll
            for (int i = 0; i < 4; i++) {
                unsigned w = 0;
#pragma unroll
                for (int j = 0; j < 4; j++) {
                    float uu = fminf(fmaxf((float)s[i][j] * cs, 0.0f), 7.0f);
                    w |= ((unsigned)(int)rintf(uu)) << (8 * j);
                }
                sm.a.as_[ty * 4 + i][tx] = (int)w;
            }
            __syncthreads();
#pragma unroll
            for (int c = 0; c < 16; c++) {
                int a[4], bb[4];
#pragma unroll
                for (int i = 0; i < 4; i++) a[i] = sm.a.as_[ty * 4 + i][c];
#pragma unroll
                for (int j = 0; j < 4; j++) bb[j] = sm.a.vs[tx * 4 + j][c];
#pragma unroll
                for (int i = 0; i < 4; i++)
#pragma unroll
                    for (int j = 0; j < 4; j++) o[i][j] = __dp4a(a[i], bb[j], o[i][j]);
            }
            __syncthreads();
        }
#pragma unroll
        for (int i = 0; i < 4; i++) {
            int n = n0 + ty * 4 + i;
#pragma unroll
            for (int j = 0; j < 4; j++) {
                int d = tx * 4 + j;
                float outv = (float)o[i][j] * ovs;
                float uu = fminf(fmaxf(outv / s_after, -4.0f), 3.0f);
                g_xo[((long)b * N_ + n) * C_ + h * D_ + d] = s_after * rintf(uu);
            }
        }
    }

    grid_sync(my_sense);

    // ---- Phase 3: out = g_xo @ Wproj^T + bias -----------------------------
    for (int tile = blockIdx.x; tile < 12 * 128; tile += GRID_) {
        const int j0 = (tile % 12) * 64;
        const int m0 = (tile / 12) * 64;
        float acc[4][4] = {};
        __syncthreads();
        for (int k0 = 0; k0 < C_; k0 += 16) {
            for (int l = tid; l < 64 * 16; l += 256) {
                int m = l >> 4, k = l & 15;
                sm.g.As[k][m] = g_xo[(long)(m0 + m) * C_ + k0 + k];
                sm.g.Bs[k][m] = Wproj[(long)(j0 + m) * C_ + k0 + k];
            }
            __syncthreads();
#pragma unroll
            for (int kk = 0; kk < 16; kk++) {
                float a[4], b[4];
#pragma unroll
                for (int i = 0; i < 4; i++) a[i] = sm.g.As[kk][ty * 4 + i];
#pragma unroll
                for (int j = 0; j < 4; j++) b[j] = sm.g.Bs[kk][tx * 4 + j];
#pragma unroll
                for (int i = 0; i < 4; i++)
#pragma unroll
                    for (int j = 0; j < 4; j++) acc[i][j] += a[i] * b[j];
            }
            __syncthreads();
        }
#pragma unroll
        for (int i = 0; i < 4; i++) {
            int m = m0 + ty * 4 + i;
#pragma unroll
            for (int j = 0; j < 4; j++) {
                int jj = j0 + tx * 4 + j;
                out[(long)m * C_ + jj] = acc[i][j] + bias[jj];
            }
        }
    }
}

// ---------------------------------------------------------------------------
extern "C" void kernel_launch(void* const* d_in, const int* in_sizes, int n_in,
                              void* d_out, int out_size) {
    const float* x      = (const float*)d_in[0];
    const float* Wqkv   = (const float*)d_in[1];
    const float* Wproj  = (const float*)d_in[2];
    const float* bproj  = (const float*)d_in[3];
    const float* s_q    = (const float*)d_in[4];
    const float* s_k    = (const float*)d_in[5];
    const float* s_v    = (const float*)d_in[6];
    const float* s_attn = (const float*)d_in[7];
    const float* s_aft  = (const float*)d_in[8];
    float* out = (float*)d_out;

    k_mono<<<GRID_, 256>>>(x, Wqkv, Wproj, bproj,
                           s_q, s_k, s_v, s_attn, s_aft, out);
}

// round 7
// speedup vs baseline: 1.8993x; 1.0072x over previous
#include <cuda_runtime.h>
#include <cstdint>

// ============================================================================
// QAttention_without_softmax (B=4, N=2048, C=768, H=12, D=64, LEVEL=8)
//
// Structure exploited (runtime-verified, general fallback kept):
//   iq,ik in [-4,3]  =>  |sum_d iq*ik| <= 64*16 = 1024
//   t = 0.125*s_q*s_k*sum/(N*s_attn); if |t|_max < 0.5 then
//   round(clip(t,0,7)) == 0 for ALL elements => attn-out == 0 => fq(0)==0
//   => final = bproj broadcast, independent of x and Wqkv.
// Benchmark scales give |t|_max = 0.4375 -> fast path, bit-exact.
//
// R6 change (fast path only): flat float4 broadcast with ALL 256 threads,
// fully unrolled 11-iteration store sweep, bias held in 3 registers
// (column pattern has period 3 because grid-stride 151552 = 64 mod 192).
// No smem, no loop-carried deps -> ptxas front-batches the STG.128s and
// the kernel should be pure L2-write-bound.
// Fallback: unchanged exact pipeline with software grid barrier
// (grid 592 = 148 SM x 4 CTA, launch_bounds(256,4) => all co-resident).
// ============================================================================

#define B_    4
#define N_    2048
#define C_    768
#define H_    12
#define D_    64
#define GRID_ 592
#define ROWS_ 8192           // B*N
#define C4_   192            // C/4
#define TOT4_ (ROWS_ * C4_)  // 1,572,864 float4 elements
#define STRIDE4_ (GRID_ * 256)  // 151,552 (== 64 mod 192)

// scratch (__device__ globals; no allocation anywhere)
__device__ int   g_q[48 * 2048 * 16];   // int8 [bh][n][d], packed 4/word
__device__ int   g_k[48 * 2048 * 16];   // int8 [bh][n][d]
__device__ int   g_v[48 * 64 * 512];    // int8 [bh][d][m], packed (transposed)
__device__ float g_xo[ROWS_ * C_];      // quantized attention output [B,N,C]

// grid-barrier state (fallback only; fast path never touches)
__device__ unsigned g_count = 0;
__device__ unsigned g_sense = 0;

__device__ __forceinline__ void grid_sync(unsigned& my_sense) {
    __threadfence();
    __syncthreads();
    ++my_sense;
    if (threadIdx.x == 0) {
        unsigned arrived = atomicAdd(&g_count, 1u);
        if (arrived == GRID_ - 1u) {
            g_count = 0u;
            __threadfence();
            atomicExch(&g_sense, my_sense);
        } else {
            while (atomicAdd(&g_sense, 0u) != my_sense) __nanosleep(64);
        }
    }
    __syncthreads();
}

__global__ __launch_bounds__(256, 4)
void k_mono(const float* __restrict__ x,     const float* __restrict__ Wqkv,
            const float* __restrict__ Wproj, const float* __restrict__ bias,
            const float* sqp, const float* skp, const float* svp,
            const float* sap, const float* sfp,
            float* __restrict__ out) {
    const int tid = threadIdx.x;

    // ---- skip predicate: attention fake-quant provably all-zero? ----------
    // |t|_max = 0.125 * |s_q*s_k| * 1024 / (N * |s_attn|)
    const float s_q = __ldg(sqp), s_k = __ldg(skp), s_attn = __ldg(sap);
    const float T = fabsf(s_q * s_k) * 128.0f / (2048.0f * fabsf(s_attn));

    if (T < 0.4999f) {
        // ===== FAST PATH: out = bproj broadcast, flat float4 sweep ==========
        const int idx0 = blockIdx.x * 256 + tid;     // float4 index
        const int col0 = idx0 % C4_;
        int c1 = col0 + 64;  if (c1 >= C4_) c1 -= C4_;
        int c2 = col0 + 128; if (c2 >= C4_) c2 -= C4_;
        const float4 bv0 = __ldg((const float4*)bias + col0);
        const float4 bv1 = __ldg((const float4*)bias + c1);
        const float4 bv2 = __ldg((const float4*)bias + c2);
        float4* o4 = (float4*)out;
#pragma unroll
        for (int i = 0; i < 11; i++) {
            const int idx = idx0 + i * STRIDE4_;
            if (idx < TOT4_) {
                const float4 bv = (i % 3 == 0) ? bv0 : (i % 3 == 1) ? bv1 : bv2;
                o4[idx] = bv;
            }
        }
        return;
    }

    // ======================= FALLBACK (exact pipeline) ======================
    const float s_v = svp[0], s_after = sfp[0];
    const int tx = tid & 15, ty = tid >> 4;
    unsigned my_sense = atomicAdd(&g_sense, 0u);   // read before any toggle

    __shared__ union {
        struct { float As[16][65], Bs[16][65]; } g;
        struct { int qs[64][16], ks[64][16], as_[64][16], vs[64][16]; } a;
    } sm;

    // ---- Phase 1: qkv = x @ Wqkv^T, fake-quant -> int8 q/k/v --------------
    for (int tile = blockIdx.x; tile < 36 * 128; tile += GRID_) {
        const int j0 = (tile % 36) * 64;       // [0,2304)
        const int m0 = (tile / 36) * 64;       // [0,8192)
        float acc[4][4] = {};
        for (int k0 = 0; k0 < C_; k0 += 16) {
            for (int l = tid; l < 64 * 16; l += 256) {
                int m = l >> 4, k = l & 15;
                sm.g.As[k][m] = x[(long)(m0 + m) * C_ + k0 + k];
                sm.g.Bs[k][m] = Wqkv[(long)(j0 + m) * C_ + k0 + k];
            }
            __syncthreads();
#pragma unroll
            for (int kk = 0; kk < 16; kk++) {
                float a[4], b[4];
#pragma unroll
                for (int i = 0; i < 4; i++) a[i] = sm.g.As[kk][ty * 4 + i];
#pragma unroll
                for (int j = 0; j < 4; j++) b[j] = sm.g.Bs[kk][tx * 4 + j];
#pragma unroll
                for (int i = 0; i < 4; i++)
#pragma unroll
                    for (int j = 0; j < 4; j++) acc[i][j] += a[i] * b[j];
            }
            __syncthreads();
        }
#pragma unroll
        for (int i = 0; i < 4; i++) {
            int m = m0 + ty * 4 + i;
            int b = m / N_, n = m - b * N_;
#pragma unroll
            for (int j = 0; j < 4; j++) {
                int jj = j0 + tx * 4 + j;
                int three = jj / C_;
                int rem = jj - three * C_;
                int h = rem >> 6, d = rem & 63;
                long bh = (long)b * H_ + h;
                float val = acc[i][j];
                if (three == 0) {
                    float u = fminf(fmaxf(val / s_q, -4.0f), 3.0f);
                    ((int8_t*)g_q)[(bh * N_ + n) * D_ + d] = (int8_t)(int)rintf(u);
                } else if (three == 1) {
                    float u = fminf(fmaxf(val / s_k, -4.0f), 3.0f);
                    ((int8_t*)g_k)[(bh * N_ + n) * D_ + d] = (int8_t)(int)rintf(u);
                } else {
                    float u = fminf(fmaxf(val / s_v, -4.0f), 3.0f);
                    ((int8_t*)g_v)[(bh * D_ + d) * N_ + n] = (int8_t)(int)rintf(u);
                }
            }
        }
    }

    grid_sync(my_sense);

    // ---- Phase 2: exact int8 dp4a attention -------------------------------
    const float cs  = 0.125f * s_q * s_k / ((float)N_ * s_attn);
    const float ovs = s_attn * s_v;
    for (int u = blockIdx.x; u < 48 * 32; u += GRID_) {
        const int bh = u >> 5;                 // 0..47
        const int n0 = (u & 31) * 64;
        const int* qw = g_q + (long)bh * N_ * 16;
        const int* kw = g_k + (long)bh * N_ * 16;
        const int* vw = g_v + (long)bh * D_ * (N_ / 4);
        const int b = bh / H_, h = bh - b * H_;

        __syncthreads();
        for (int l = tid; l < 64 * 16; l += 256) {
            int r = l >> 4, c = l & 15;
            sm.a.qs[r][c] = qw[(n0 + r) * 16 + c];
        }

        int o[4][4] = {};
        for (int m0 = 0; m0 < N_; m0 += 64) {
            for (int l = tid; l < 64 * 16; l += 256) {
                int r = l >> 4, c = l & 15;
                sm.a.ks[r][c] = kw[(m0 + r) * 16 + c];
                sm.a.vs[r][c] = vw[r * (N_ / 4) + (m0 >> 2) + c];
            }
            __syncthreads();

            int s[4][4] = {};
#pragma unroll
            for (int c = 0; c < 16; c++) {
                int a[4], bb[4];
#pragma unroll
                for (int i = 0; i < 4; i++) a[i] = sm.a.qs[ty * 4 + i][c];
#pragma unroll
                for (int j = 0; j < 4; j++) bb[j] = sm.a.ks[tx * 4 + j][c];
#pragma unroll
                for (int i = 0; i < 4; i++)
#pragma unroll
                    for (int j = 0; j < 4; j++) s[i][j] = __dp4a(a[i], bb[j], s[i][j]);
            }
#pragma unroll
            for (int i = 0; i < 4; i++) {
                unsigned w = 0;
#pragma unroll
                for (int j = 0; j < 4; j++) {
                    float uu = fminf(fmaxf((float)s[i][j] * cs, 0.0f), 7.0f);
                    w |= ((unsigned)(int)rintf(uu)) << (8 * j);
                }
                sm.a.as_[ty * 4 + i][tx] = (int)w;
            }
            __syncthreads();
#pragma unroll
            for (int c = 0; c < 16; c++) {
                int a[4], bb[4];
#pragma unroll
                for (int i = 0; i < 4; i++) a[i] = sm.a.as_[ty * 4 + i][c];
#pragma unroll
                for (int j = 0; j < 4; j++) bb[j] = sm.a.vs[tx * 4 + j][c];
#pragma unroll
                for (int i = 0; i < 4; i++)
#pragma unroll
                    for (int j = 0; j < 4; j++) o[i][j] = __dp4a(a[i], bb[j], o[i][j]);
            }
            __syncthreads();
        }
#pragma unroll
        for (int i = 0; i < 4; i++) {
            int n = n0 + ty * 4 + i;
#pragma unroll
            for (int j = 0; j < 4; j++) {
                int d = tx * 4 + j;
                float outv = (float)o[i][j] * ovs;
                float uu = fminf(fmaxf(outv / s_after, -4.0f), 3.0f);
                g_xo[((long)b * N_ + n) * C_ + h * D_ + d] = s_after * rintf(uu);
            }
        }
    }

    grid_sync(my_sense);

    // ---- Phase 3: out = g_xo @ Wproj^T + bias -----------------------------
    for (int tile = blockIdx.x; tile < 12 * 128; tile += GRID_) {
        const int j0 = (tile % 12) * 64;
        const int m0 = (tile / 12) * 64;
        float acc[4][4] = {};
        __syncthreads();
        for (int k0 = 0; k0 < C_; k0 += 16) {
            for (int l = tid; l < 64 * 16; l += 256) {
                int m = l >> 4, k = l & 15;
                sm.g.As[k][m] = g_xo[(long)(m0 + m) * C_ + k0 + k];
                sm.g.Bs[k][m] = Wproj[(long)(j0 + m) * C_ + k0 + k];
            }
            __syncthreads();
#pragma unroll
            for (int kk = 0; kk < 16; kk++) {
                float a[4], b[4];
#pragma unroll
                for (int i = 0; i < 4; i++) a[i] = sm.g.As[kk][ty * 4 + i];
#pragma unroll
                for (int j = 0; j < 4; j++) b[j] = sm.g.Bs[kk][tx * 4 + j];
#pragma unroll
                for (int i = 0; i < 4; i++)
#pragma unroll
                    for (int j = 0; j < 4; j++) acc[i][j] += a[i] * b[j];
            }
            __syncthreads();
        }
#pragma unroll
        for (int i = 0; i < 4; i++) {
            int m = m0 + ty * 4 + i;
#pragma unroll
            for (int j = 0; j < 4; j++) {
                int jj = j0 + tx * 4 + j;
                out[(long)m * C_ + jj] = acc[i][j] + bias[jj];
            }
        }
    }
}

// ---------------------------------------------------------------------------
extern "C" void kernel_launch(void* const* d_in, const int* in_sizes, int n_in,
                              void* d_out, int out_size) {
    const float* x      = (const float*)d_in[0];
    const float* Wqkv   = (const float*)d_in[1];
    const float* Wproj  = (const float*)d_in[2];
    const float* bproj  = (const float*)d_in[3];
    const float* s_q    = (const float*)d_in[4];
    const float* s_k    = (const float*)d_in[5];
    const float* s_v    = (const float*)d_in[6];
    const float* s_attn = (const float*)d_in[7];
    const float* s_aft  = (const float*)d_in[8];
    float* out = (float*)d_out;

    k_mono<<<GRID_, 256>>>(x, Wqkv, Wproj, bproj,
                           s_q, s_k, s_v, s_attn, s_aft, out);
}